// round 7
// baseline (speedup 1.0000x reference)
#include <cuda_runtime.h>
#include <stdint.h>

// SmoothLDDTLoss — b=2, n=4096. Fused single kernel, scalar inner loop
// (sm_100a has no native FFMA2 — R6 showed f32x2 PTX gets expanded + MOVs).
// Expansion-form distances on sqrt(2)*LOG2E-scaled coords; per-j radius in
// smem + FSEL; coords_mask via +1e30 poison; 1 rcp per 2 pairs.

#define TILE 128

__device__ double       g_sum[2];
__device__ double       g_cnt[2];
__device__ unsigned int g_done;

__device__ __forceinline__ float fsqrt_ap(float x) { float r; asm("sqrt.approx.f32 %0, %1;" : "=f"(r) : "f"(x)); return r; }
__device__ __forceinline__ float frcp_ap (float x) { float r; asm("rcp.approx.f32 %0, %1;"  : "=f"(r) : "f"(x)); return r; }
__device__ __forceinline__ float fex2_ap (float x) { float r; asm("ex2.approx.f32 %0, %1;"  : "=f"(r) : "f"(x)); return r; }

#define SC     2.04022209793536f     /* sqrt(2)*LOG2E */
#define L2     2.08136899f           /* LOG2E^2 */
#define CLAMP  14.4269504088896f     /* 10*LOG2E — keeps dens finite, rescues NaN */
#define R225   (225.0f * L2)
#define R900   (900.0f * L2)
// sigmoid constants e^{-0.5}, e^{-1}, e^{-2}, e^{-4}
#define C1 0.60653065971263342f
#define C2 0.36787944117144233f
#define C3 0.13533528323661270f
#define C4 0.01831563888873418f

// per-pair numerator / denominator of (sum of 4 sigmoids)
__device__ __forceinline__ void eps_parts(float dt2, float dp2, float& num, float& den)
{
    float st = fsqrt_ap(fmaxf(dt2, 0.0f));
    float sp = fsqrt_ap(fmaxf(dp2, 0.0f));
    float diff = fminf(fabsf(st - sp), CLAMP);      // log2-domain distance diff
    float e  = fex2_ap(diff);                       // e^{diff_linear}
    float u1 = fmaf(e, C1, 1.0f);
    float u2 = fmaf(e, C2, 1.0f);
    float u3 = fmaf(e, C3, 1.0f);
    float u4 = fmaf(e, C4, 1.0f);
    float A = u1 * u2, B = u3 * u4;
    num = fmaf(u1 + u2, B, (u3 + u4) * A);
    den = A * B;
}

template<bool DIAG>
__device__ __forceinline__ void tile_loop(
    const float4* __restrict__ sP,   // px,py,pz, sqp   (scaled)
    const float4* __restrict__ sT,   // tx,ty,tz, sqt   (scaled, poisoned if masked)
    const float*  __restrict__ sR,   // r2j in {R225, R900}, 0 if j>=n
    float nix, float niy, float niz, float ntx, float nty, float ntz,
    float sqip, float sqit, bool inuc, int ig, int jbase,
    float& acc_sum, float& acc_cnt)
{
    #pragma unroll 4
    for (int q = 0; q < TILE; q += 2) {
        float4 P0 = sP[q],     T0 = sT[q];
        float4 P1 = sP[q + 1], T1 = sT[q + 1];
        float  r20 = sR[q],    r21 = sR[q + 1];

        float dp20 = fmaf(nix, P0.x, fmaf(niy, P0.y, fmaf(niz, P0.z, sqip + P0.w)));
        float dt20 = fmaf(ntx, T0.x, fmaf(nty, T0.y, fmaf(ntz, T0.z, sqit + T0.w)));
        float dp21 = fmaf(nix, P1.x, fmaf(niy, P1.y, fmaf(niz, P1.z, sqip + P1.w)));
        float dt21 = fmaf(ntx, T1.x, fmaf(nty, T1.y, fmaf(ntz, T1.z, sqit + T1.w)));

        float num0, den0, num1, den1;
        eps_parts(dt20, dp20, num0, den0);
        eps_parts(dt21, dp21, num1, den1);

        float r    = frcp_ap(den0 * den1);          // one rcp, two pairs
        float eps0 = num0 * (r * den1);
        float eps1 = num1 * (r * den0);

        float R20 = inuc ? r20 : R225;              // min(ri2, r2j) exact
        float R21 = inuc ? r21 : R225;
        bool v0 = dt20 < R20;
        bool v1 = dt21 < R21;
        if (DIAG) {
            v0 = v0 && (jbase + q     > ig);
            v1 = v1 && (jbase + q + 1 > ig);
        }
        acc_sum += v0 ? eps0 : 0.0f;
        acc_sum += v1 ? eps1 : 0.0f;
        acc_cnt += v0 ? 1.0f : 0.0f;
        acc_cnt += v1 ? 1.0f : 0.0f;
    }
}

__global__ void __launch_bounds__(TILE) lddt_fused_kernel(
    const float* __restrict__ pred,
    const float* __restrict__ truec,
    const uint8_t* __restrict__ is_dna,
    const uint8_t* __restrict__ is_rna,
    const uint8_t* __restrict__ cmask,
    float* __restrict__ out,
    int n, int ntiles, unsigned int total_blocks)
{
    // closed-form triangular decode: blockIdx.x -> (ti, tj), ti <= tj
    int t = blockIdx.x;
    float Nf = (float)ntiles;
    float disc = fmaf(2.0f, Nf, 1.0f);
    float s    = sqrtf(fmaf(disc, disc, -8.0f * (float)t));
    int ti = (int)floorf(0.5f * (disc - s));
    if (ti < 0) ti = 0;
    if (ti > ntiles - 1) ti = ntiles - 1;
    #pragma unroll
    for (int k = 0; k < 2; k++) {
        int row_off  = ti * ntiles - (ti * (ti - 1)) / 2;
        int next_off = (ti + 1) * ntiles - ((ti + 1) * ti) / 2;
        if (t < row_off)        ti--;
        else if (t >= next_off) ti++;
    }
    int row_off = ti * ntiles - (ti * (ti - 1)) / 2;
    int tj = ti + (t - row_off);
    if (tj < ti) tj = ti;
    if (tj > ntiles - 1) tj = ntiles - 1;

    const int b = blockIdx.y;
    const int tid = threadIdx.x;
    const long base = (long)b * n;

    __shared__ float4 sP[TILE];
    __shared__ float4 sT[TILE];
    __shared__ float  sR[TILE];

    // ---- fill j tile ----
    {
        int jg = tj * TILE + tid;
        float4 P = make_float4(0.f, 0.f, 0.f, 0.f);
        float4 T = make_float4(0.f, 0.f, 0.f, 1e30f);   // poisoned by default
        float r2 = 0.0f;                                 // never passes cutoff
        if (jg < n) {
            long idx = (base + jg) * 3;
            P.x = pred[idx + 0] * SC; P.y = pred[idx + 1] * SC; P.z = pred[idx + 2] * SC;
            T.x = truec[idx + 0] * SC; T.y = truec[idx + 1] * SC; T.z = truec[idx + 2] * SC;
            P.w = 0.5f * fmaf(P.x, P.x, fmaf(P.y, P.y, P.z * P.z));   // L2*|p|^2
            T.w = 0.5f * fmaf(T.x, T.x, fmaf(T.y, T.y, T.z * T.z));
            bool nuc = (__ldg(&is_dna[base + jg]) | __ldg(&is_rna[base + jg])) != 0;
            r2 = nuc ? R900 : R225;
            if (!__ldg(&cmask[base + jg])) T.w += 1e30f;
        }
        sP[tid] = P;
        sT[tid] = T;
        sR[tid] = r2;
    }
    __syncthreads();

    // ---- own i point (negated scaled coords for the fma-dot chain) ----
    const int ig = ti * TILE + tid;
    float nix = 0.f, niy = 0.f, niz = 0.f, ntx = 0.f, nty = 0.f, ntz = 0.f;
    float sqip = 0.f, sqit = 1e30f;
    bool inuc = false;
    if (ig < n) {
        long idx = (base + ig) * 3;
        float ax = pred[idx + 0] * SC, ay = pred[idx + 1] * SC, az = pred[idx + 2] * SC;
        float bx = truec[idx + 0] * SC, by = truec[idx + 1] * SC, bz = truec[idx + 2] * SC;
        sqip = 0.5f * fmaf(ax, ax, fmaf(ay, ay, az * az));
        sqit = 0.5f * fmaf(bx, bx, fmaf(by, by, bz * bz));
        nix = -ax; niy = -ay; niz = -az;
        ntx = -bx; nty = -by; ntz = -bz;
        inuc = (__ldg(&is_dna[base + ig]) | __ldg(&is_rna[base + ig])) != 0;
        if (!__ldg(&cmask[base + ig])) sqit += 1e30f;
    }

    float acc_sum = 0.f, acc_cnt = 0.f;
    const int jbase = tj * TILE;
    if (ti == tj)
        tile_loop<true >(sP, sT, sR, nix, niy, niz, ntx, nty, ntz, sqip, sqit, inuc, ig, jbase, acc_sum, acc_cnt);
    else
        tile_loop<false>(sP, sT, sR, nix, niy, niz, ntx, nty, ntz, sqip, sqit, inuc, ig, jbase, acc_sum, acc_cnt);

    // ---- block reduce ----
    #pragma unroll
    for (int o = 16; o > 0; o >>= 1) {
        acc_sum += __shfl_down_sync(0xFFFFFFFFu, acc_sum, o);
        acc_cnt += __shfl_down_sync(0xFFFFFFFFu, acc_cnt, o);
    }
    __shared__ float ws[TILE / 32];
    __shared__ float wc[TILE / 32];
    int w = tid >> 5, l = tid & 31;
    if (l == 0) { ws[w] = acc_sum; wc[w] = acc_cnt; }
    __syncthreads();

    if (tid == 0) {
        float S = 0.f, C = 0.f;
        #pragma unroll
        for (int k = 0; k < TILE / 32; k++) { S += ws[k]; C += wc[k]; }
        atomicAdd(&g_sum[b], (double)S * 0.25);
        atomicAdd(&g_cnt[b], (double)C);

        __threadfence();
        unsigned int done = atomicAdd(&g_done, 1u);
        if (done == total_blocks - 1u) {
            volatile double* vs = g_sum;
            volatile double* vc = g_cnt;
            double c0 = vc[0]; if (c0 < 1.0) c0 = 1.0;
            double c1 = vc[1]; if (c1 < 1.0) c1 = 1.0;
            double l0 = vs[0] / c0;
            double l1 = vs[1] / c1;
            out[0] = (float)(1.0 - 0.5 * (l0 + l1));
            g_sum[0] = 0.0; g_sum[1] = 0.0;
            g_cnt[0] = 0.0; g_cnt[1] = 0.0;
            __threadfence();
            g_done = 0u;
        }
    }
}

extern "C" void kernel_launch(void* const* d_in, const int* in_sizes, int n_in,
                              void* d_out, int out_size)
{
    const float*   pred  = (const float*)d_in[0];
    const float*   truec = (const float*)d_in[1];
    const uint8_t* dna   = (const uint8_t*)d_in[2];
    const uint8_t* rna   = (const uint8_t*)d_in[3];
    const uint8_t* cm    = (const uint8_t*)d_in[4];

    const int B = 2;
    const int n = in_sizes[2] / B;
    const int ntiles = (n + TILE - 1) / TILE;
    const int npairs = ntiles * (ntiles + 1) / 2;

    dim3 grid(npairs, B);
    lddt_fused_kernel<<<grid, TILE>>>(pred, truec, dna, rna, cm,
                                      (float*)d_out, n, ntiles,
                                      (unsigned int)(npairs * B));
}

// round 8
// speedup vs baseline: 1.1397x; 1.1397x over previous
#include <cuda_runtime.h>
#include <stdint.h>

// SmoothLDDTLoss — b=2, n=4096. Fused single kernel.
// f32x2-packed distance + sigmoid chains (R6, proven fastest), scalar MUFU
// section and lean scalar tail. Expansion-form distances on sqrt(2)*LOG2E-
// scaled coords; per-j radius in smem; coords_mask via +1e30 poison;
// 1 rcp per 2 pairs; no d2 clamps (cancellation-negative d2 is benign).

#define TILE 128
#define QN   (TILE / 2)

typedef unsigned long long ull;

__device__ double       g_sum[2];
__device__ double       g_cnt[2];
__device__ unsigned int g_done;

__device__ __forceinline__ float fsqrt_ap(float x) { float r; asm("sqrt.approx.f32 %0, %1;" : "=f"(r) : "f"(x)); return r; }
__device__ __forceinline__ float frcp_ap (float x) { float r; asm("rcp.approx.f32 %0, %1;"  : "=f"(r) : "f"(x)); return r; }
__device__ __forceinline__ float fex2_ap (float x) { float r; asm("ex2.approx.f32 %0, %1;"  : "=f"(r) : "f"(x)); return r; }

__device__ __forceinline__ ull pk2(float lo, float hi) { ull r; asm("mov.b64 %0, {%1, %2};" : "=l"(r) : "f"(lo), "f"(hi)); return r; }
__device__ __forceinline__ void upk2(float& lo, float& hi, ull v) { asm("mov.b64 {%0, %1}, %2;" : "=f"(lo), "=f"(hi) : "l"(v)); }
__device__ __forceinline__ ull fma2(ull a, ull b, ull c) { ull d; asm("fma.rn.f32x2 %0, %1, %2, %3;" : "=l"(d) : "l"(a), "l"(b), "l"(c)); return d; }
__device__ __forceinline__ ull mul2(ull a, ull b) { ull d; asm("mul.rn.f32x2 %0, %1, %2;" : "=l"(d) : "l"(a), "l"(b)); return d; }
__device__ __forceinline__ ull add2(ull a, ull b) { ull d; asm("add.rn.f32x2 %0, %1, %2;" : "=l"(d) : "l"(a), "l"(b)); return d; }

#define SC     2.04022209793536f     /* sqrt(2)*LOG2E */
#define L2     2.08136899f           /* LOG2E^2 */
#define CLAMP  14.4269504088896f     /* 10*LOG2E — keeps dens finite, rescues NaN */
#define R225   (225.0f * L2)
#define R900   (900.0f * L2)
// sigmoid constants e^{-0.5}, e^{-1}, e^{-2}, e^{-4}
#define C1 0.60653065971263342f
#define C2 0.36787944117144233f
#define C3 0.13533528323661270f
#define C4 0.01831563888873418f

// smem layout per q (pair of j points), 10 u64 = 20 floats:
// v0:(pxp,pyp) v1:(pzp,txp) v2:(typ,tzp) v3:(sqpp,sqtp) v4:(r2p,pad)
struct SmemQ { ulonglong2 v[5]; };

template<bool DIAG>
__device__ __forceinline__ void tile_loop(
    const SmemQ* __restrict__ W,
    ull nix2, ull niy2, ull niz2, ull ntx2, ull nty2, ull ntz2,
    ull sqip2, ull sqit2, bool inuc, int ig, int jbase,
    float& as0, float& as1, float& ac0, float& ac1,
    ull K1, ull K2, ull K3, ull K4, ull ONE2)
{
    #pragma unroll 4
    for (int q = 0; q < QN; q++) {
        ulonglong2 g0 = W[q].v[0];
        ulonglong2 g1 = W[q].v[1];
        ulonglong2 g2 = W[q].v[2];
        ulonglong2 g3 = W[q].v[3];
        ull r2p       = W[q].v[4].x;

        ull dp2p = fma2(nix2, g0.x, fma2(niy2, g0.y, fma2(niz2, g1.x, add2(sqip2, g3.x))));
        ull dt2p = fma2(ntx2, g1.y, fma2(nty2, g2.x, fma2(ntz2, g2.y, add2(sqit2, g3.y))));

        float dp0, dp1, dt0, dt1;
        upk2(dp0, dp1, dp2p);
        upk2(dt0, dt1, dt2p);

        float sp0 = fsqrt_ap(dp0), sp1 = fsqrt_ap(dp1);
        float st0 = fsqrt_ap(dt0), st1 = fsqrt_ap(dt1);

        float f0 = fminf(fabsf(st0 - sp0), CLAMP);
        float f1 = fminf(fabsf(st1 - sp1), CLAMP);
        float e0 = fex2_ap(f0);
        float e1 = fex2_ap(f1);
        ull e2 = pk2(e0, e1);

        ull u1 = fma2(e2, K1, ONE2);
        ull u2 = fma2(e2, K2, ONE2);
        ull u3 = fma2(e2, K3, ONE2);
        ull u4 = fma2(e2, K4, ONE2);
        ull A2 = mul2(u1, u2), B2 = mul2(u3, u4);
        ull s12 = add2(u1, u2), s34 = add2(u3, u4);
        ull num2 = fma2(s12, B2, mul2(s34, A2));
        ull den2 = mul2(A2, B2);

        float n0, n1, d0, d1;
        upk2(n0, n1, num2);
        upk2(d0, d1, den2);
        float r    = frcp_ap(d0 * d1);          // one rcp, two pairs
        float eps0 = n0 * (r * d1);
        float eps1 = n1 * (r * d0);

        float r20, r21;
        upk2(r20, r21, r2p);
        float R20 = inuc ? r20 : R225;          // min(ri2, r2j) exact
        float R21 = inuc ? r21 : R225;
        bool v0 = dt0 < R20;
        bool v1 = dt1 < R21;
        if (DIAG) {
            v0 = v0 && (jbase + 2 * q     > ig);
            v1 = v1 && (jbase + 2 * q + 1 > ig);
        }
        as0 += v0 ? eps0 : 0.0f;
        as1 += v1 ? eps1 : 0.0f;
        ac0 += v0 ? 1.0f : 0.0f;
        ac1 += v1 ? 1.0f : 0.0f;
    }
}

__global__ void __launch_bounds__(TILE) lddt_fused_kernel(
    const float* __restrict__ pred,
    const float* __restrict__ truec,
    const uint8_t* __restrict__ is_dna,
    const uint8_t* __restrict__ is_rna,
    const uint8_t* __restrict__ cmask,
    float* __restrict__ out,
    int n, int ntiles, unsigned int total_blocks)
{
    // closed-form triangular decode: blockIdx.x -> (ti, tj), ti <= tj
    int t = blockIdx.x;
    float Nf = (float)ntiles;
    float disc = fmaf(2.0f, Nf, 1.0f);
    float s    = sqrtf(fmaf(disc, disc, -8.0f * (float)t));
    int ti = (int)floorf(0.5f * (disc - s));
    if (ti < 0) ti = 0;
    if (ti > ntiles - 1) ti = ntiles - 1;
    #pragma unroll
    for (int k = 0; k < 2; k++) {
        int row_off  = ti * ntiles - (ti * (ti - 1)) / 2;
        int next_off = (ti + 1) * ntiles - ((ti + 1) * ti) / 2;
        if (t < row_off)        ti--;
        else if (t >= next_off) ti++;
    }
    int row_off = ti * ntiles - (ti * (ti - 1)) / 2;
    int tj = ti + (t - row_off);
    if (tj < ti) tj = ti;
    if (tj > ntiles - 1) tj = ntiles - 1;

    const int b = blockIdx.y;
    const int tid = threadIdx.x;
    const long base = (long)b * n;

    __shared__ SmemQ W[QN];

    // ---- fill j tile ----
    {
        int jg = tj * TILE + tid;
        float px = 0.f, py = 0.f, pz = 0.f, tx = 0.f, ty = 0.f, tz = 0.f;
        float sqp = 0.f, sqt = 1e30f, r2 = 0.f;   // default: poisoned & zero radius
        if (jg < n) {
            long idx = (base + jg) * 3;
            px = pred[idx + 0] * SC; py = pred[idx + 1] * SC; pz = pred[idx + 2] * SC;
            tx = truec[idx + 0] * SC; ty = truec[idx + 1] * SC; tz = truec[idx + 2] * SC;
            sqp = 0.5f * fmaf(px, px, fmaf(py, py, pz * pz));     // = L2*|p|^2
            sqt = 0.5f * fmaf(tx, tx, fmaf(ty, ty, tz * tz));
            bool nuc = (__ldg(&is_dna[base + jg]) | __ldg(&is_rna[base + jg])) != 0;
            r2 = nuc ? R900 : R225;
            if (!__ldg(&cmask[base + jg])) sqt += 1e30f;
        }
        float* F = (float*)W;
        int q = tid >> 1, l = tid & 1;
        int o = q * 20 + l;
        F[o +  0] = px;  F[o +  2] = py;  F[o +  4] = pz;
        F[o +  6] = tx;  F[o +  8] = ty;  F[o + 10] = tz;
        F[o + 12] = sqp; F[o + 14] = sqt; F[o + 16] = r2;
    }
    __syncthreads();

    // ---- own i point (negated scaled coords for the fma-dot chain) ----
    const int ig = ti * TILE + tid;
    float nix = 0.f, niy = 0.f, niz = 0.f, ntx = 0.f, nty = 0.f, ntz = 0.f;
    float sqip = 0.f, sqit = 1e30f;
    bool inuc = false;
    if (ig < n) {
        long idx = (base + ig) * 3;
        float ax = pred[idx + 0] * SC, ay = pred[idx + 1] * SC, az = pred[idx + 2] * SC;
        float bx = truec[idx + 0] * SC, by = truec[idx + 1] * SC, bz = truec[idx + 2] * SC;
        sqip = 0.5f * fmaf(ax, ax, fmaf(ay, ay, az * az));
        sqit = 0.5f * fmaf(bx, bx, fmaf(by, by, bz * bz));
        nix = -ax; niy = -ay; niz = -az;
        ntx = -bx; nty = -by; ntz = -bz;
        inuc = (__ldg(&is_dna[base + ig]) | __ldg(&is_rna[base + ig])) != 0;
        if (!__ldg(&cmask[base + ig])) sqit += 1e30f;
    }

    ull nix2 = pk2(nix, nix), niy2 = pk2(niy, niy), niz2 = pk2(niz, niz);
    ull ntx2 = pk2(ntx, ntx), nty2 = pk2(nty, nty), ntz2 = pk2(ntz, ntz);
    ull sqip2 = pk2(sqip, sqip), sqit2 = pk2(sqit, sqit);
    ull K1 = pk2(C1, C1), K2 = pk2(C2, C2), K3 = pk2(C3, C3), K4 = pk2(C4, C4);
    ull ONE2 = pk2(1.0f, 1.0f);

    float as0 = 0.f, as1 = 0.f, ac0 = 0.f, ac1 = 0.f;
    const int jbase = tj * TILE;
    if (ti == tj)
        tile_loop<true >(W, nix2, niy2, niz2, ntx2, nty2, ntz2, sqip2, sqit2, inuc, ig, jbase, as0, as1, ac0, ac1, K1, K2, K3, K4, ONE2);
    else
        tile_loop<false>(W, nix2, niy2, niz2, ntx2, nty2, ntz2, sqip2, sqit2, inuc, ig, jbase, as0, as1, ac0, ac1, K1, K2, K3, K4, ONE2);

    float acc_sum = as0 + as1;
    float acc_cnt = ac0 + ac1;

    // ---- block reduce ----
    #pragma unroll
    for (int o = 16; o > 0; o >>= 1) {
        acc_sum += __shfl_down_sync(0xFFFFFFFFu, acc_sum, o);
        acc_cnt += __shfl_down_sync(0xFFFFFFFFu, acc_cnt, o);
    }
    __shared__ float ws[TILE / 32];
    __shared__ float wc[TILE / 32];
    int w = tid >> 5, l = tid & 31;
    if (l == 0) { ws[w] = acc_sum; wc[w] = acc_cnt; }
    __syncthreads();

    if (tid == 0) {
        float S = 0.f, C = 0.f;
        #pragma unroll
        for (int k = 0; k < TILE / 32; k++) { S += ws[k]; C += wc[k]; }
        atomicAdd(&g_sum[b], (double)S * 0.25);
        atomicAdd(&g_cnt[b], (double)C);

        __threadfence();
        unsigned int done = atomicAdd(&g_done, 1u);
        if (done == total_blocks - 1u) {
            volatile double* vs = g_sum;
            volatile double* vc = g_cnt;
            double c0 = vc[0]; if (c0 < 1.0) c0 = 1.0;
            double c1 = vc[1]; if (c1 < 1.0) c1 = 1.0;
            double l0 = vs[0] / c0;
            double l1 = vs[1] / c1;
            out[0] = (float)(1.0 - 0.5 * (l0 + l1));
            g_sum[0] = 0.0; g_sum[1] = 0.0;
            g_cnt[0] = 0.0; g_cnt[1] = 0.0;
            __threadfence();
            g_done = 0u;
        }
    }
}

extern "C" void kernel_launch(void* const* d_in, const int* in_sizes, int n_in,
                              void* d_out, int out_size)
{
    const float*   pred  = (const float*)d_in[0];
    const float*   truec = (const float*)d_in[1];
    const uint8_t* dna   = (const uint8_t*)d_in[2];
    const uint8_t* rna   = (const uint8_t*)d_in[3];
    const uint8_t* cm    = (const uint8_t*)d_in[4];

    const int B = 2;
    const int n = in_sizes[2] / B;
    const int ntiles = (n + TILE - 1) / TILE;
    const int npairs = ntiles * (ntiles + 1) / 2;

    dim3 grid(npairs, B);
    lddt_fused_kernel<<<grid, TILE>>>(pred, truec, dna, rna, cm,
                                      (float*)d_out, n, ntiles,
                                      (unsigned int)(npairs * B));
}

// round 9
// speedup vs baseline: 1.1677x; 1.0246x over previous
#include <cuda_runtime.h>
#include <stdint.h>

// SmoothLDDTLoss — b=2, n=4096. Fused single kernel, scalar-minimal loop.
// sm_100a: f32x2 PTX expands to 2xFFMA + MOVs (measured R6-R8), so pure
// scalar with minimal slot count wins. TILE=64 / 64-thread blocks for
// ~75% occupancy. Expansion-form distances on sqrt(2)*LOG2E-scaled coords;
// per-pair radii in smem; coords_mask via +1e30 poison; 1 rcp per 2 pairs.

#define TILE 64
#define QN   (TILE / 2)

__device__ double       g_sum[2];
__device__ double       g_cnt[2];
__device__ unsigned int g_done;

__device__ __forceinline__ float fsqrt_ap(float x) { float r; asm("sqrt.approx.f32 %0, %1;" : "=f"(r) : "f"(x)); return r; }
__device__ __forceinline__ float frcp_ap (float x) { float r; asm("rcp.approx.f32 %0, %1;"  : "=f"(r) : "f"(x)); return r; }
__device__ __forceinline__ float fex2_ap (float x) { float r; asm("ex2.approx.f32 %0, %1;"  : "=f"(r) : "f"(x)); return r; }

#define SC     2.04022209793536f     /* sqrt(2)*LOG2E */
#define L2     2.08136899f           /* LOG2E^2 */
#define CLAMP  14.4269504088896f     /* 10*LOG2E */
#define R225   (225.0f * L2)
#define R900   (900.0f * L2)
// sigmoid constants e^{-0.5}, e^{-1}, e^{-2}, e^{-4}
#define C1 0.60653065971263342f
#define C2 0.36787944117144233f
#define C3 0.13533528323661270f
#define C4 0.01831563888873418f

// 80-byte stride per 2-j group: one base pointer + immediate offsets.
struct __align__(16) SmemG {
    float4 P0, T0, P1, T1;   // (px,py,pz,sqp) / (tx,ty,tz,sqt) per j
    float2 R;                // (r2_0, r2_1)
    float2 pad;
};

__device__ __forceinline__ void pair_eps(float dt2, float dp2, float& num, float& den)
{
    float st = fsqrt_ap(dt2);
    float sp = fsqrt_ap(dp2);
    float diff = fminf(fabsf(st - sp), CLAMP);
    float e  = fex2_ap(diff);
    float u1 = fmaf(e, C1, 1.0f);
    float u2 = fmaf(e, C2, 1.0f);
    float u3 = fmaf(e, C3, 1.0f);
    float u4 = fmaf(e, C4, 1.0f);
    float A = u1 * u2, B = u3 * u4;
    num = fmaf(u1 + u2, B, (u3 + u4) * A);
    den = A * B;
}

template<bool DIAG>
__device__ __forceinline__ void tile_loop(
    const SmemG* __restrict__ W,
    float nix, float niy, float niz, float ntx, float nty, float ntz,
    float sqip, float sqit, bool inuc, int ig, int jbase,
    float& as0, float& as1, float& ac0, float& ac1)
{
    #pragma unroll 4
    for (int q = 0; q < QN; q++) {
        const SmemG* g = W + q;
        float4 P0 = g->P0, T0 = g->T0;
        float4 P1 = g->P1, T1 = g->T1;
        float2 R  = g->R;

        float dp20 = fmaf(nix, P0.x, fmaf(niy, P0.y, fmaf(niz, P0.z, sqip + P0.w)));
        float dt20 = fmaf(ntx, T0.x, fmaf(nty, T0.y, fmaf(ntz, T0.z, sqit + T0.w)));
        float dp21 = fmaf(nix, P1.x, fmaf(niy, P1.y, fmaf(niz, P1.z, sqip + P1.w)));
        float dt21 = fmaf(ntx, T1.x, fmaf(nty, T1.y, fmaf(ntz, T1.z, sqit + T1.w)));

        float num0, den0, num1, den1;
        pair_eps(dt20, dp20, num0, den0);
        pair_eps(dt21, dp21, num1, den1);

        float r    = frcp_ap(den0 * den1);      // one rcp, two pairs
        float eps0 = num0 * (r * den1);
        float eps1 = num1 * (r * den0);

        float R20 = inuc ? R.x : R225;          // = min(ri2, r2j) exactly
        float R21 = inuc ? R.y : R225;
        bool v0 = dt20 < R20;
        bool v1 = dt21 < R21;
        if (DIAG) {
            v0 = v0 && (jbase + 2 * q     > ig);
            v1 = v1 && (jbase + 2 * q + 1 > ig);
        }
        if (v0) { as0 += eps0; ac0 += 1.0f; }
        if (v1) { as1 += eps1; ac1 += 1.0f; }
    }
}

__global__ void __launch_bounds__(TILE, 24) lddt_fused_kernel(
    const float* __restrict__ pred,
    const float* __restrict__ truec,
    const uint8_t* __restrict__ is_dna,
    const uint8_t* __restrict__ is_rna,
    const uint8_t* __restrict__ cmask,
    float* __restrict__ out,
    int n, int ntiles, unsigned int total_blocks)
{
    // closed-form triangular decode: blockIdx.x -> (ti, tj), ti <= tj
    int t = blockIdx.x;
    float Nf = (float)ntiles;
    float disc = fmaf(2.0f, Nf, 1.0f);
    float s    = sqrtf(fmaf(disc, disc, -8.0f * (float)t));
    int ti = (int)floorf(0.5f * (disc - s));
    if (ti < 0) ti = 0;
    if (ti > ntiles - 1) ti = ntiles - 1;
    #pragma unroll
    for (int k = 0; k < 2; k++) {
        int row_off  = ti * ntiles - (ti * (ti - 1)) / 2;
        int next_off = (ti + 1) * ntiles - ((ti + 1) * ti) / 2;
        if (t < row_off)        ti--;
        else if (t >= next_off) ti++;
    }
    int row_off = ti * ntiles - (ti * (ti - 1)) / 2;
    int tj = ti + (t - row_off);
    if (tj < ti) tj = ti;
    if (tj > ntiles - 1) tj = ntiles - 1;

    const int b = blockIdx.y;
    const int tid = threadIdx.x;
    const long base = (long)b * n;

    __shared__ SmemG W[QN];

    // ---- fill j tile ----
    {
        int jg = tj * TILE + tid;
        float4 P = make_float4(0.f, 0.f, 0.f, 0.f);
        float4 T = make_float4(0.f, 0.f, 0.f, 1e30f);   // poisoned default
        float r2 = R225;
        if (jg < n) {
            long idx = (base + jg) * 3;
            P.x = pred[idx + 0] * SC; P.y = pred[idx + 1] * SC; P.z = pred[idx + 2] * SC;
            T.x = truec[idx + 0] * SC; T.y = truec[idx + 1] * SC; T.z = truec[idx + 2] * SC;
            P.w = 0.5f * fmaf(P.x, P.x, fmaf(P.y, P.y, P.z * P.z));   // = L2*|p|^2
            T.w = 0.5f * fmaf(T.x, T.x, fmaf(T.y, T.y, T.z * T.z));
            bool nuc = (__ldg(&is_dna[base + jg]) | __ldg(&is_rna[base + jg])) != 0;
            r2 = nuc ? R900 : R225;
            if (!__ldg(&cmask[base + jg])) T.w += 1e30f;
        }
        int q = tid >> 1, l = tid & 1;
        if (l == 0) { W[q].P0 = P; W[q].T0 = T; W[q].R.x = r2; }
        else        { W[q].P1 = P; W[q].T1 = T; W[q].R.y = r2; }
    }
    __syncthreads();

    // ---- own i point (negated scaled coords for the fma-dot chain) ----
    const int ig = ti * TILE + tid;
    float nix = 0.f, niy = 0.f, niz = 0.f, ntx = 0.f, nty = 0.f, ntz = 0.f;
    float sqip = 0.f, sqit = 1e30f;
    bool inuc = false;
    if (ig < n) {
        long idx = (base + ig) * 3;
        float ax = pred[idx + 0] * SC, ay = pred[idx + 1] * SC, az = pred[idx + 2] * SC;
        float bx = truec[idx + 0] * SC, by = truec[idx + 1] * SC, bz = truec[idx + 2] * SC;
        sqip = 0.5f * fmaf(ax, ax, fmaf(ay, ay, az * az));
        sqit = 0.5f * fmaf(bx, bx, fmaf(by, by, bz * bz));
        nix = -ax; niy = -ay; niz = -az;
        ntx = -bx; nty = -by; ntz = -bz;
        inuc = (__ldg(&is_dna[base + ig]) | __ldg(&is_rna[base + ig])) != 0;
        if (!__ldg(&cmask[base + ig])) sqit += 1e30f;
    }

    float as0 = 0.f, as1 = 0.f, ac0 = 0.f, ac1 = 0.f;
    const int jbase = tj * TILE;
    if (ti == tj)
        tile_loop<true >(W, nix, niy, niz, ntx, nty, ntz, sqip, sqit, inuc, ig, jbase, as0, as1, ac0, ac1);
    else
        tile_loop<false>(W, nix, niy, niz, ntx, nty, ntz, sqip, sqit, inuc, ig, jbase, as0, as1, ac0, ac1);

    float acc_sum = as0 + as1;
    float acc_cnt = ac0 + ac1;

    // ---- block reduce (64 threads = 2 warps) ----
    #pragma unroll
    for (int o = 16; o > 0; o >>= 1) {
        acc_sum += __shfl_down_sync(0xFFFFFFFFu, acc_sum, o);
        acc_cnt += __shfl_down_sync(0xFFFFFFFFu, acc_cnt, o);
    }
    __shared__ float ws[2], wc[2];
    if ((tid & 31) == 0) { ws[tid >> 5] = acc_sum; wc[tid >> 5] = acc_cnt; }
    __syncthreads();

    if (tid == 0) {
        float S = ws[0] + ws[1];
        float C = wc[0] + wc[1];
        atomicAdd(&g_sum[b], (double)S * 0.25);
        atomicAdd(&g_cnt[b], (double)C);

        __threadfence();
        unsigned int done = atomicAdd(&g_done, 1u);
        if (done == total_blocks - 1u) {
            volatile double* vs = g_sum;
            volatile double* vc = g_cnt;
            double c0 = vc[0]; if (c0 < 1.0) c0 = 1.0;
            double c1 = vc[1]; if (c1 < 1.0) c1 = 1.0;
            double l0 = vs[0] / c0;
            double l1 = vs[1] / c1;
            out[0] = (float)(1.0 - 0.5 * (l0 + l1));
            g_sum[0] = 0.0; g_sum[1] = 0.0;
            g_cnt[0] = 0.0; g_cnt[1] = 0.0;
            __threadfence();
            g_done = 0u;
        }
    }
}

extern "C" void kernel_launch(void* const* d_in, const int* in_sizes, int n_in,
                              void* d_out, int out_size)
{
    const float*   pred  = (const float*)d_in[0];
    const float*   truec = (const float*)d_in[1];
    const uint8_t* dna   = (const uint8_t*)d_in[2];
    const uint8_t* rna   = (const uint8_t*)d_in[3];
    const uint8_t* cm    = (const uint8_t*)d_in[4];

    const int B = 2;
    const int n = in_sizes[2] / B;
    const int ntiles = (n + TILE - 1) / TILE;
    const int npairs = ntiles * (ntiles + 1) / 2;

    dim3 grid(npairs, B);
    lddt_fused_kernel<<<grid, TILE>>>(pred, truec, dna, rna, cm,
                                      (float*)d_out, n, ntiles,
                                      (unsigned int)(npairs * B));
}

// round 11
// speedup vs baseline: 1.1763x; 1.0073x over previous
#include <cuda_runtime.h>
#include <stdint.h>

// SmoothLDDTLoss — b=2, n=4096. Fused single kernel, scalar-minimal loop.
// R11 (= R10 with macro-collision fixed): branchless select accumulation +
// symmetric-polynomial sigmoid sum  sum_k 1/(1+c_k e) = P(e)/Q(e), Horner.
// Expansion-form distances on sqrt(2)*LOG2E-scaled coords; TILE=64 blocks;
// coords_mask via +1e30 poison; 1 rcp per 2 pairs.

#define TILE 64
#define QN   (TILE / 2)

__device__ double       g_sum[2];
__device__ double       g_cnt[2];
__device__ unsigned int g_done;

__device__ __forceinline__ float fsqrt_ap(float x) { float r; asm("sqrt.approx.f32 %0, %1;" : "=f"(r) : "f"(x)); return r; }
__device__ __forceinline__ float frcp_ap (float x) { float r; asm("rcp.approx.f32 %0, %1;"  : "=f"(r) : "f"(x)); return r; }
__device__ __forceinline__ float fex2_ap (float x) { float r; asm("ex2.approx.f32 %0, %1;"  : "=f"(r) : "f"(x)); return r; }

constexpr float SC    = 2.04022209793536f;    // sqrt(2)*LOG2E
constexpr float L2C   = 2.08136899f;          // LOG2E^2
constexpr float CLAMP = 14.4269504088896f;    // 10*LOG2E
constexpr float R225  = 225.0f * L2C;
constexpr float R900  = 900.0f * L2C;

// Elementary symmetric functions of c = {e^-0.5, e^-1, e^-2, e^-4}:
// sum_k 1/(1+c_k e) = PP(e)/QQ(e)
// PP = 4 + 3*ES1 e + 2*ES2 e^2 + ES3 e^3
// QQ = 1 + ES1 e + ES2 e^2 + ES3 e^3 + ES4 e^4
constexpr float ES1 = 1.12806064f;
constexpr float ES2 = 0.37532785f;
constexpr float ES3 = 0.03669949f;
constexpr float ES4 = 0.000553084f;
constexpr float PC1 = 3.0f * ES1;
constexpr float PC2 = 2.0f * ES2;

// 80-byte stride per 2-j group: one base pointer + immediate offsets.
struct __align__(16) SmemG {
    float4 Pa, Ta, Pb, Tb;   // (px,py,pz,sqp) / (tx,ty,tz,sqt) for j0, j1
    float2 R;                // (r2_j0, r2_j1)
    float2 pad;
};

// per-pair numerator / denominator of (sum of 4 sigmoids) = PP(e)/QQ(e)
__device__ __forceinline__ void pair_eps(float dt2, float dp2, float& num, float& den)
{
    float st = fsqrt_ap(dt2);
    float sp = fsqrt_ap(dp2);
    float diff = fminf(fabsf(st - sp), CLAMP);
    float e  = fex2_ap(diff);
    num = fmaf(fmaf(fmaf(ES3, e, PC2), e, PC1), e, 4.0f);
    den = fmaf(fmaf(fmaf(fmaf(ES4, e, ES3), e, ES2), e, ES1), e, 1.0f);
}

template<bool DIAG>
__device__ __forceinline__ void tile_loop(
    const SmemG* __restrict__ W,
    float nix, float niy, float niz, float ntx, float nty, float ntz,
    float sqip, float sqit, bool inuc, int ig, int jbase,
    float& as0, float& as1, float& ac0, float& ac1)
{
    #pragma unroll 4
    for (int q = 0; q < QN; q++) {
        const SmemG* g = W + q;
        float4 Pa = g->Pa, Ta = g->Ta;
        float4 Pb = g->Pb, Tb = g->Tb;
        float2 R  = g->R;

        float dp20 = fmaf(nix, Pa.x, fmaf(niy, Pa.y, fmaf(niz, Pa.z, sqip + Pa.w)));
        float dt20 = fmaf(ntx, Ta.x, fmaf(nty, Ta.y, fmaf(ntz, Ta.z, sqit + Ta.w)));
        float dp21 = fmaf(nix, Pb.x, fmaf(niy, Pb.y, fmaf(niz, Pb.z, sqip + Pb.w)));
        float dt21 = fmaf(ntx, Tb.x, fmaf(nty, Tb.y, fmaf(ntz, Tb.z, sqit + Tb.w)));

        float num0, den0, num1, den1;
        pair_eps(dt20, dp20, num0, den0);
        pair_eps(dt21, dp21, num1, den1);

        float r    = frcp_ap(den0 * den1);      // one rcp, two pairs
        float eps0 = num0 * (r * den1);
        float eps1 = num1 * (r * den0);

        float R20 = inuc ? R.x : R225;          // = min(ri2, r2j) exactly
        float R21 = inuc ? R.y : R225;
        bool v0 = dt20 < R20;
        bool v1 = dt21 < R21;
        if (DIAG) {
            v0 = v0 && (jbase + 2 * q     > ig);
            v1 = v1 && (jbase + 2 * q + 1 > ig);
        }
        // branchless: FSEL + FADD, no BSSY/BSYNC
        as0 += v0 ? eps0 : 0.0f;
        as1 += v1 ? eps1 : 0.0f;
        ac0 += v0 ? 1.0f : 0.0f;
        ac1 += v1 ? 1.0f : 0.0f;
    }
}

__global__ void __launch_bounds__(TILE, 24) lddt_fused_kernel(
    const float* __restrict__ pred,
    const float* __restrict__ truec,
    const uint8_t* __restrict__ is_dna,
    const uint8_t* __restrict__ is_rna,
    const uint8_t* __restrict__ cmask,
    float* __restrict__ out,
    int n, int ntiles, unsigned int total_blocks)
{
    // closed-form triangular decode: blockIdx.x -> (ti, tj), ti <= tj
    int t = blockIdx.x;
    float Nf = (float)ntiles;
    float disc = fmaf(2.0f, Nf, 1.0f);
    float s    = sqrtf(fmaf(disc, disc, -8.0f * (float)t));
    int ti = (int)floorf(0.5f * (disc - s));
    if (ti < 0) ti = 0;
    if (ti > ntiles - 1) ti = ntiles - 1;
    #pragma unroll
    for (int k = 0; k < 2; k++) {
        int row_off  = ti * ntiles - (ti * (ti - 1)) / 2;
        int next_off = (ti + 1) * ntiles - ((ti + 1) * ti) / 2;
        if (t < row_off)        ti--;
        else if (t >= next_off) ti++;
    }
    int row_off = ti * ntiles - (ti * (ti - 1)) / 2;
    int tj = ti + (t - row_off);
    if (tj < ti) tj = ti;
    if (tj > ntiles - 1) tj = ntiles - 1;

    const int b = blockIdx.y;
    const int tid = threadIdx.x;
    const long base = (long)b * n;

    __shared__ SmemG W[QN];

    // ---- fill j tile ----
    {
        int jg = tj * TILE + tid;
        float4 P = make_float4(0.f, 0.f, 0.f, 0.f);
        float4 T = make_float4(0.f, 0.f, 0.f, 1e30f);   // poisoned default
        float r2 = R225;
        if (jg < n) {
            long idx = (base + jg) * 3;
            P.x = pred[idx + 0] * SC; P.y = pred[idx + 1] * SC; P.z = pred[idx + 2] * SC;
            T.x = truec[idx + 0] * SC; T.y = truec[idx + 1] * SC; T.z = truec[idx + 2] * SC;
            P.w = 0.5f * fmaf(P.x, P.x, fmaf(P.y, P.y, P.z * P.z));   // = L2C*|p|^2
            T.w = 0.5f * fmaf(T.x, T.x, fmaf(T.y, T.y, T.z * T.z));
            bool nuc = (__ldg(&is_dna[base + jg]) | __ldg(&is_rna[base + jg])) != 0;
            r2 = nuc ? R900 : R225;
            if (!__ldg(&cmask[base + jg])) T.w += 1e30f;
        }
        int q = tid >> 1, l = tid & 1;
        if (l == 0) { W[q].Pa = P; W[q].Ta = T; W[q].R.x = r2; }
        else        { W[q].Pb = P; W[q].Tb = T; W[q].R.y = r2; }
    }
    __syncthreads();

    // ---- own i point (negated scaled coords for the fma-dot chain) ----
    const int ig = ti * TILE + tid;
    float nix = 0.f, niy = 0.f, niz = 0.f, ntx = 0.f, nty = 0.f, ntz = 0.f;
    float sqip = 0.f, sqit = 1e30f;
    bool inuc = false;
    if (ig < n) {
        long idx = (base + ig) * 3;
        float ax = pred[idx + 0] * SC, ay = pred[idx + 1] * SC, az = pred[idx + 2] * SC;
        float bx = truec[idx + 0] * SC, by = truec[idx + 1] * SC, bz = truec[idx + 2] * SC;
        sqip = 0.5f * fmaf(ax, ax, fmaf(ay, ay, az * az));
        sqit = 0.5f * fmaf(bx, bx, fmaf(by, by, bz * bz));
        nix = -ax; niy = -ay; niz = -az;
        ntx = -bx; nty = -by; ntz = -bz;
        inuc = (__ldg(&is_dna[base + ig]) | __ldg(&is_rna[base + ig])) != 0;
        if (!__ldg(&cmask[base + ig])) sqit += 1e30f;
    }

    float as0 = 0.f, as1 = 0.f, ac0 = 0.f, ac1 = 0.f;
    const int jbase = tj * TILE;
    if (ti == tj)
        tile_loop<true >(W, nix, niy, niz, ntx, nty, ntz, sqip, sqit, inuc, ig, jbase, as0, as1, ac0, ac1);
    else
        tile_loop<false>(W, nix, niy, niz, ntx, nty, ntz, sqip, sqit, inuc, ig, jbase, as0, as1, ac0, ac1);

    float acc_sum = as0 + as1;
    float acc_cnt = ac0 + ac1;

    // ---- block reduce (64 threads = 2 warps) ----
    #pragma unroll
    for (int o = 16; o > 0; o >>= 1) {
        acc_sum += __shfl_down_sync(0xFFFFFFFFu, acc_sum, o);
        acc_cnt += __shfl_down_sync(0xFFFFFFFFu, acc_cnt, o);
    }
    __shared__ float ws[2], wc[2];
    if ((tid & 31) == 0) { ws[tid >> 5] = acc_sum; wc[tid >> 5] = acc_cnt; }
    __syncthreads();

    if (tid == 0) {
        float S = ws[0] + ws[1];
        float C = wc[0] + wc[1];
        atomicAdd(&g_sum[b], (double)S * 0.25);
        atomicAdd(&g_cnt[b], (double)C);

        __threadfence();
        unsigned int done = atomicAdd(&g_done, 1u);
        if (done == total_blocks - 1u) {
            volatile double* vs = g_sum;
            volatile double* vc = g_cnt;
            double c0 = vc[0]; if (c0 < 1.0) c0 = 1.0;
            double c1 = vc[1]; if (c1 < 1.0) c1 = 1.0;
            double l0 = vs[0] / c0;
            double l1 = vs[1] / c1;
            out[0] = (float)(1.0 - 0.5 * (l0 + l1));
            g_sum[0] = 0.0; g_sum[1] = 0.0;
            g_cnt[0] = 0.0; g_cnt[1] = 0.0;
            __threadfence();
            g_done = 0u;
        }
    }
}

extern "C" void kernel_launch(void* const* d_in, const int* in_sizes, int n_in,
                              void* d_out, int out_size)
{
    const float*   pred  = (const float*)d_in[0];
    const float*   truec = (const float*)d_in[1];
    const uint8_t* dna   = (const uint8_t*)d_in[2];
    const uint8_t* rna   = (const uint8_t*)d_in[3];
    const uint8_t* cm    = (const uint8_t*)d_in[4];

    const int B = 2;
    const int n = in_sizes[2] / B;
    const int ntiles = (n + TILE - 1) / TILE;
    const int npairs = ntiles * (ntiles + 1) / 2;

    dim3 grid(npairs, B);
    lddt_fused_kernel<<<grid, TILE>>>(pred, truec, dna, rna, cm,
                                      (float*)d_out, n, ntiles,
                                      (unsigned int)(npairs * B));
}

// round 12
// speedup vs baseline: 1.1774x; 1.0009x over previous
#include <cuda_runtime.h>
#include <stdint.h>

// SmoothLDDTLoss — b=2, n=4096. Fused single kernel, scalar-minimal loop.
// R11 (= R10 with macro-collision fixed): branchless select accumulation +
// symmetric-polynomial sigmoid sum  sum_k 1/(1+c_k e) = P(e)/Q(e), Horner.
// Expansion-form distances on sqrt(2)*LOG2E-scaled coords; TILE=64 blocks;
// coords_mask via +1e30 poison; 1 rcp per 2 pairs.

#define TILE 64
#define QN   (TILE / 2)

__device__ double       g_sum[2];
__device__ double       g_cnt[2];
__device__ unsigned int g_done;

__device__ __forceinline__ float fsqrt_ap(float x) { float r; asm("sqrt.approx.f32 %0, %1;" : "=f"(r) : "f"(x)); return r; }
__device__ __forceinline__ float frcp_ap (float x) { float r; asm("rcp.approx.f32 %0, %1;"  : "=f"(r) : "f"(x)); return r; }
__device__ __forceinline__ float fex2_ap (float x) { float r; asm("ex2.approx.f32 %0, %1;"  : "=f"(r) : "f"(x)); return r; }

constexpr float SC    = 2.04022209793536f;    // sqrt(2)*LOG2E
constexpr float L2C   = 2.08136899f;          // LOG2E^2
constexpr float CLAMP = 14.4269504088896f;    // 10*LOG2E
constexpr float R225  = 225.0f * L2C;
constexpr float R900  = 900.0f * L2C;

// Elementary symmetric functions of c = {e^-0.5, e^-1, e^-2, e^-4}:
// sum_k 1/(1+c_k e) = PP(e)/QQ(e)
// PP = 4 + 3*ES1 e + 2*ES2 e^2 + ES3 e^3
// QQ = 1 + ES1 e + ES2 e^2 + ES3 e^3 + ES4 e^4
constexpr float ES1 = 1.12806064f;
constexpr float ES2 = 0.37532785f;
constexpr float ES3 = 0.03669949f;
constexpr float ES4 = 0.000553084f;
constexpr float PC1 = 3.0f * ES1;
constexpr float PC2 = 2.0f * ES2;

// 80-byte stride per 2-j group: one base pointer + immediate offsets.
struct __align__(16) SmemG {
    float4 Pa, Ta, Pb, Tb;   // (px,py,pz,sqp) / (tx,ty,tz,sqt) for j0, j1
    float2 R;                // (r2_j0, r2_j1)
    float2 pad;
};

// per-pair numerator / denominator of (sum of 4 sigmoids) = PP(e)/QQ(e)
__device__ __forceinline__ void pair_eps(float dt2, float dp2, float& num, float& den)
{
    float st = fsqrt_ap(dt2);
    float sp = fsqrt_ap(dp2);
    float diff = fminf(fabsf(st - sp), CLAMP);
    float e  = fex2_ap(diff);
    num = fmaf(fmaf(fmaf(ES3, e, PC2), e, PC1), e, 4.0f);
    den = fmaf(fmaf(fmaf(fmaf(ES4, e, ES3), e, ES2), e, ES1), e, 1.0f);
}

template<bool DIAG>
__device__ __forceinline__ void tile_loop(
    const SmemG* __restrict__ W,
    float nix, float niy, float niz, float ntx, float nty, float ntz,
    float sqip, float sqit, bool inuc, int ig, int jbase,
    float& as0, float& as1, float& ac0, float& ac1)
{
    #pragma unroll 4
    for (int q = 0; q < QN; q++) {
        const SmemG* g = W + q;
        float4 Pa = g->Pa, Ta = g->Ta;
        float4 Pb = g->Pb, Tb = g->Tb;
        float2 R  = g->R;

        float dp20 = fmaf(nix, Pa.x, fmaf(niy, Pa.y, fmaf(niz, Pa.z, sqip + Pa.w)));
        float dt20 = fmaf(ntx, Ta.x, fmaf(nty, Ta.y, fmaf(ntz, Ta.z, sqit + Ta.w)));
        float dp21 = fmaf(nix, Pb.x, fmaf(niy, Pb.y, fmaf(niz, Pb.z, sqip + Pb.w)));
        float dt21 = fmaf(ntx, Tb.x, fmaf(nty, Tb.y, fmaf(ntz, Tb.z, sqit + Tb.w)));

        float num0, den0, num1, den1;
        pair_eps(dt20, dp20, num0, den0);
        pair_eps(dt21, dp21, num1, den1);

        float r    = frcp_ap(den0 * den1);      // one rcp, two pairs
        float eps0 = num0 * (r * den1);
        float eps1 = num1 * (r * den0);

        float R20 = inuc ? R.x : R225;          // = min(ri2, r2j) exactly
        float R21 = inuc ? R.y : R225;
        bool v0 = dt20 < R20;
        bool v1 = dt21 < R21;
        if (DIAG) {
            v0 = v0 && (jbase + 2 * q     > ig);
            v1 = v1 && (jbase + 2 * q + 1 > ig);
        }
        // branchless: FSEL + FADD, no BSSY/BSYNC
        as0 += v0 ? eps0 : 0.0f;
        as1 += v1 ? eps1 : 0.0f;
        ac0 += v0 ? 1.0f : 0.0f;
        ac1 += v1 ? 1.0f : 0.0f;
    }
}

__global__ void __launch_bounds__(TILE, 24) lddt_fused_kernel(
    const float* __restrict__ pred,
    const float* __restrict__ truec,
    const uint8_t* __restrict__ is_dna,
    const uint8_t* __restrict__ is_rna,
    const uint8_t* __restrict__ cmask,
    float* __restrict__ out,
    int n, int ntiles, unsigned int total_blocks)
{
    // closed-form triangular decode: blockIdx.x -> (ti, tj), ti <= tj
    int t = blockIdx.x;
    float Nf = (float)ntiles;
    float disc = fmaf(2.0f, Nf, 1.0f);
    float s    = sqrtf(fmaf(disc, disc, -8.0f * (float)t));
    int ti = (int)floorf(0.5f * (disc - s));
    if (ti < 0) ti = 0;
    if (ti > ntiles - 1) ti = ntiles - 1;
    #pragma unroll
    for (int k = 0; k < 2; k++) {
        int row_off  = ti * ntiles - (ti * (ti - 1)) / 2;
        int next_off = (ti + 1) * ntiles - ((ti + 1) * ti) / 2;
        if (t < row_off)        ti--;
        else if (t >= next_off) ti++;
    }
    int row_off = ti * ntiles - (ti * (ti - 1)) / 2;
    int tj = ti + (t - row_off);
    if (tj < ti) tj = ti;
    if (tj > ntiles - 1) tj = ntiles - 1;

    const int b = blockIdx.y;
    const int tid = threadIdx.x;
    const long base = (long)b * n;

    __shared__ SmemG W[QN];

    // ---- fill j tile ----
    {
        int jg = tj * TILE + tid;
        float4 P = make_float4(0.f, 0.f, 0.f, 0.f);
        float4 T = make_float4(0.f, 0.f, 0.f, 1e30f);   // poisoned default
        float r2 = R225;
        if (jg < n) {
            long idx = (base + jg) * 3;
            P.x = pred[idx + 0] * SC; P.y = pred[idx + 1] * SC; P.z = pred[idx + 2] * SC;
            T.x = truec[idx + 0] * SC; T.y = truec[idx + 1] * SC; T.z = truec[idx + 2] * SC;
            P.w = 0.5f * fmaf(P.x, P.x, fmaf(P.y, P.y, P.z * P.z));   // = L2C*|p|^2
            T.w = 0.5f * fmaf(T.x, T.x, fmaf(T.y, T.y, T.z * T.z));
            bool nuc = (__ldg(&is_dna[base + jg]) | __ldg(&is_rna[base + jg])) != 0;
            r2 = nuc ? R900 : R225;
            if (!__ldg(&cmask[base + jg])) T.w += 1e30f;
        }
        int q = tid >> 1, l = tid & 1;
        if (l == 0) { W[q].Pa = P; W[q].Ta = T; W[q].R.x = r2; }
        else        { W[q].Pb = P; W[q].Tb = T; W[q].R.y = r2; }
    }
    __syncthreads();

    // ---- own i point (negated scaled coords for the fma-dot chain) ----
    const int ig = ti * TILE + tid;
    float nix = 0.f, niy = 0.f, niz = 0.f, ntx = 0.f, nty = 0.f, ntz = 0.f;
    float sqip = 0.f, sqit = 1e30f;
    bool inuc = false;
    if (ig < n) {
        long idx = (base + ig) * 3;
        float ax = pred[idx + 0] * SC, ay = pred[idx + 1] * SC, az = pred[idx + 2] * SC;
        float bx = truec[idx + 0] * SC, by = truec[idx + 1] * SC, bz = truec[idx + 2] * SC;
        sqip = 0.5f * fmaf(ax, ax, fmaf(ay, ay, az * az));
        sqit = 0.5f * fmaf(bx, bx, fmaf(by, by, bz * bz));
        nix = -ax; niy = -ay; niz = -az;
        ntx = -bx; nty = -by; ntz = -bz;
        inuc = (__ldg(&is_dna[base + ig]) | __ldg(&is_rna[base + ig])) != 0;
        if (!__ldg(&cmask[base + ig])) sqit += 1e30f;
    }

    float as0 = 0.f, as1 = 0.f, ac0 = 0.f, ac1 = 0.f;
    const int jbase = tj * TILE;
    if (ti == tj)
        tile_loop<true >(W, nix, niy, niz, ntx, nty, ntz, sqip, sqit, inuc, ig, jbase, as0, as1, ac0, ac1);
    else
        tile_loop<false>(W, nix, niy, niz, ntx, nty, ntz, sqip, sqit, inuc, ig, jbase, as0, as1, ac0, ac1);

    float acc_sum = as0 + as1;
    float acc_cnt = ac0 + ac1;

    // ---- block reduce (64 threads = 2 warps) ----
    #pragma unroll
    for (int o = 16; o > 0; o >>= 1) {
        acc_sum += __shfl_down_sync(0xFFFFFFFFu, acc_sum, o);
        acc_cnt += __shfl_down_sync(0xFFFFFFFFu, acc_cnt, o);
    }
    __shared__ float ws[2], wc[2];
    if ((tid & 31) == 0) { ws[tid >> 5] = acc_sum; wc[tid >> 5] = acc_cnt; }
    __syncthreads();

    if (tid == 0) {
        float S = ws[0] + ws[1];
        float C = wc[0] + wc[1];
        atomicAdd(&g_sum[b], (double)S * 0.25);
        atomicAdd(&g_cnt[b], (double)C);

        __threadfence();
        unsigned int done = atomicAdd(&g_done, 1u);
        if (done == total_blocks - 1u) {
            volatile double* vs = g_sum;
            volatile double* vc = g_cnt;
            double c0 = vc[0]; if (c0 < 1.0) c0 = 1.0;
            double c1 = vc[1]; if (c1 < 1.0) c1 = 1.0;
            double l0 = vs[0] / c0;
            double l1 = vs[1] / c1;
            out[0] = (float)(1.0 - 0.5 * (l0 + l1));
            g_sum[0] = 0.0; g_sum[1] = 0.0;
            g_cnt[0] = 0.0; g_cnt[1] = 0.0;
            __threadfence();
            g_done = 0u;
        }
    }
}

extern "C" void kernel_launch(void* const* d_in, const int* in_sizes, int n_in,
                              void* d_out, int out_size)
{
    const float*   pred  = (const float*)d_in[0];
    const float*   truec = (const float*)d_in[1];
    const uint8_t* dna   = (const uint8_t*)d_in[2];
    const uint8_t* rna   = (const uint8_t*)d_in[3];
    const uint8_t* cm    = (const uint8_t*)d_in[4];

    const int B = 2;
    const int n = in_sizes[2] / B;
    const int ntiles = (n + TILE - 1) / TILE;
    const int npairs = ntiles * (ntiles + 1) / 2;

    dim3 grid(npairs, B);
    lddt_fused_kernel<<<grid, TILE>>>(pred, truec, dna, rna, cm,
                                      (float*)d_out, n, ntiles,
                                      (unsigned int)(npairs * B));
}